// round 13
// baseline (speedup 1.0000x reference)
#include <cuda_runtime.h>
#include <cuda_bf16.h>
#include <cstdint>

#define NT   8192   // tokens
#define DD   1024   // model dim
#define HH   4096   // hidden dim
#define NE   8      // experts
#define NENT 16384
#define NENT_PAD 16512

// ------------------------- device scratch (no allocs) -------------------------
__device__ int8_t g_w1q_hi[(size_t)NE * HH * DD];  // [E][H][D] (n-major, k contig)
__device__ int8_t g_w1q_lo[(size_t)NE * HH * DD];
__device__ int8_t g_w2q_hi[(size_t)NE * DD * HH];  // [E][D][H]
__device__ int8_t g_w2q_lo[(size_t)NE * DD * HH];
__device__ int8_t g_xq_hi [(size_t)NENT_PAD * DD];
__device__ int8_t g_xq_lo [(size_t)NENT_PAD * DD];
__device__ int8_t g_hq_hi [(size_t)NENT_PAD * HH];
__device__ int8_t g_hq_lo [(size_t)NENT_PAD * HH];
__device__ float  g_h [(size_t)NENT_PAD * HH];     // fp32 h (pre-quant)
__device__ float  g_y [(size_t)NENT_PAD * DD];
__device__ float  g_sa[NENT_PAD];
__device__ float  g_sh[NENT_PAD];
__device__ float  g_sw1[NE * HH];
__device__ float  g_sw2[NE * DD];
__device__ float  g_wts[NT * 2];
__device__ int    g_list[NE * NT];
__device__ int    g_t2e [NT * 2];
__device__ int    g_cnt [NE];

// ------------------------- helpers -------------------------
__device__ __forceinline__ uint32_t s2u(const void* p) {
    return (uint32_t)__cvta_generic_to_shared(p);
}
// gelu(x) = x * sigmoid(2*0.79788456*(x + 0.044715 x^3)); matches tanh-gelu to ~1e-7
__device__ __forceinline__ float gelu_fast(float x) {
    float z = x * fmaf(0.10294324f, x * x, 2.30220822f);  // 2u*log2(e)
    float ex; asm("ex2.approx.f32 %0, %1;" : "=f"(ex) : "f"(-z));
    float r;  asm("rcp.approx.f32 %0, %1;" : "=f"(r)  : "f"(1.0f + ex));
    return x * r;
}
__device__ __forceinline__ void cp16(uint32_t s, const void* g) {
    asm volatile("cp.async.cg.shared.global [%0], [%1], 16;" :: "r"(s), "l"(g));
}
__device__ __forceinline__ void ldm4(uint32_t a[4], uint32_t addr) {
    asm volatile("ldmatrix.sync.aligned.m8n8.x4.shared.b16 {%0,%1,%2,%3}, [%4];"
                 : "=r"(a[0]), "=r"(a[1]), "=r"(a[2]), "=r"(a[3]) : "r"(addr));
}
__device__ __forceinline__ void imma32(int d[4], const uint32_t a[4],
                                       uint32_t b0, uint32_t b1) {
    asm volatile(
        "mma.sync.aligned.m16n8k32.row.col.s32.s8.s8.s32 "
        "{%0,%1,%2,%3}, {%4,%5,%6,%7}, {%8,%9}, {%0,%1,%2,%3};"
        : "+r"(d[0]), "+r"(d[1]), "+r"(d[2]), "+r"(d[3])
        : "r"(a[0]), "r"(a[1]), "r"(a[2]), "r"(a[3]), "r"(b0), "r"(b1));
}
__device__ __forceinline__ int expert_base(int e) {
    int b = 0;
    #pragma unroll
    for (int i = 0; i < NE; i++) b += (i < e) ? g_cnt[i] : 0;
    return b;
}
__device__ __forceinline__ void quant2(float v, float inv_s, int8_t& hi, int8_t& lo) {
    float r = v * inv_s;                       // |r| <= 127
    int h = __float2int_rn(r);
    int l = __float2int_rn((r - (float)h) * 128.0f);
    hi = (int8_t)h; lo = (int8_t)l;
}

// ------------------------- small kernels -------------------------
__global__ void moe_reset_kernel() {
    if (threadIdx.x < NE) g_cnt[threadIdx.x] = 0;
}

// per-(e, out-col n) max over k of |w|;  w layout [E][K][N]
__global__ void moe_wscale_kernel(const float* __restrict__ w,
                                  float* __restrict__ sw, int K, int N) {
    int e = blockIdx.y;
    int n = blockIdx.x * 256 + threadIdx.x;
    const float* base = w + (size_t)e * K * N + n;
    float m = 0.f;
    for (int k = 0; k < K; k++) m = fmaxf(m, fabsf(base[(size_t)k * N]));
    sw[e * N + n] = m * (1.0f / 127.0f);
}

// quantize + transpose: w [E][K][N] -> hi/lo planes [E][N][K]
__global__ void moe_wquant_kernel(const float* __restrict__ w,
                                  const float* __restrict__ sw,
                                  int8_t* __restrict__ qhi,
                                  int8_t* __restrict__ qlo, int K, int N) {
    __shared__ float t[32][33];
    int e  = blockIdx.z;
    int n0 = blockIdx.x * 32, k0 = blockIdx.y * 32;
    const float* s = w + (size_t)e * K * N;
    int tx = threadIdx.x;
    #pragma unroll
    for (int i = threadIdx.y; i < 32; i += 8)
        t[i][tx] = s[(size_t)(k0 + i) * N + n0 + tx];
    __syncthreads();
    #pragma unroll
    for (int i = threadIdx.y; i < 32; i += 8) {
        int n = n0 + i;
        float sv = sw[e * N + n];
        float inv = (sv > 0.f) ? (1.0f / sv) : 0.f;
        int8_t hi, lo;
        quant2(t[tx][i], inv, hi, lo);
        size_t o = ((size_t)e * N + n) * K + k0 + tx;
        qhi[o] = hi; qlo[o] = lo;
    }
}

__global__ void moe_gate_kernel(const float* __restrict__ x,
                                const float* __restrict__ gw,
                                const float* __restrict__ gb) {
    int warp = threadIdx.x >> 5, lane = threadIdx.x & 31;
    int t = blockIdx.x * 8 + warp;
    float acc[NE];
    #pragma unroll
    for (int e = 0; e < NE; e++) acc[e] = 0.f;
    const float* xr = x + (size_t)t * DD;
    for (int k = lane; k < DD; k += 32) {
        float xv = xr[k];
        const float4* g4 = (const float4*)(gw + (size_t)k * NE);
        float4 a = g4[0], b = g4[1];
        acc[0] = fmaf(xv, a.x, acc[0]); acc[1] = fmaf(xv, a.y, acc[1]);
        acc[2] = fmaf(xv, a.z, acc[2]); acc[3] = fmaf(xv, a.w, acc[3]);
        acc[4] = fmaf(xv, b.x, acc[4]); acc[5] = fmaf(xv, b.y, acc[5]);
        acc[6] = fmaf(xv, b.z, acc[6]); acc[7] = fmaf(xv, b.w, acc[7]);
    }
    #pragma unroll
    for (int off = 16; off > 0; off >>= 1)
        #pragma unroll
        for (int e = 0; e < NE; e++)
            acc[e] += __shfl_xor_sync(0xFFFFFFFFu, acc[e], off);
    if (lane == 0) {
        float l[NE];
        #pragma unroll
        for (int e = 0; e < NE; e++) l[e] = acc[e] + gb[e];
        int i0 = 0;
        #pragma unroll
        for (int e = 1; e < NE; e++) if (l[e] > l[i0]) i0 = e;
        int i1 = (i0 == 0) ? 1 : 0;
        #pragma unroll
        for (int e = 0; e < NE; e++) if (e != i0 && l[e] > l[i1]) i1 = e;
        float ex = __expf(l[i1] - l[i0]);
        float s  = 1.0f + ex;
        int s0 = atomicAdd(&g_cnt[i0], 1);
        g_list[i0 * NT + s0] = t * 2;
        int s1 = atomicAdd(&g_cnt[i1], 1);
        g_list[i1 * NT + s1] = t * 2 + 1;
        g_wts[t * 2]     = 1.0f / s;
        g_wts[t * 2 + 1] = ex / s;
    }
}

// gather x rows per entry + two-limb quantize (per-row scale)
__global__ void moe_gatherq_kernel(const float* __restrict__ x) {
    __shared__ float red[256];
    int e = blockIdx.y;
    int cnt = g_cnt[e], base = expert_base(e);
    int tid = threadIdx.x;
    for (int slot = blockIdx.x; slot < cnt; slot += gridDim.x) {
        int tokj  = g_list[e * NT + slot];
        int entry = base + slot;
        if (tid == 0) g_t2e[tokj] = entry;
        float4 v = ((const float4*)(x + (size_t)(tokj >> 1) * DD))[tid];
        float mx = fmaxf(fmaxf(fabsf(v.x), fabsf(v.y)),
                         fmaxf(fabsf(v.z), fabsf(v.w)));
        red[tid] = mx; __syncthreads();
        for (int o = 128; o > 0; o >>= 1) {
            if (tid < o) red[tid] = fmaxf(red[tid], red[tid + o]);
            __syncthreads();
        }
        float rowmax = red[0];
        float inv = (rowmax > 0.f) ? (127.0f / rowmax) : 0.f;
        if (tid == 0) g_sa[entry] = rowmax * (1.0f / 127.0f);
        int8_t h0, h1, h2, h3, l0, l1, l2, l3;
        quant2(v.x, inv, h0, l0); quant2(v.y, inv, h1, l1);
        quant2(v.z, inv, h2, l2); quant2(v.w, inv, h3, l3);
        char4 ch = make_char4(h0, h1, h2, h3);
        char4 cl = make_char4(l0, l1, l2, l3);
        ((char4*)g_xq_hi)[(size_t)entry * (DD / 4) + tid] = ch;
        ((char4*)g_xq_lo)[(size_t)entry * (DD / 4) + tid] = cl;
        __syncthreads();
    }
}

// quantize h rows (per-row scale)
__global__ void moe_hquant_kernel() {
    __shared__ float red[256];
    int entry = blockIdx.x;
    int tid = threadIdx.x;
    const float4* src = (const float4*)(g_h + (size_t)entry * HH);
    float4 v[4];
    float mx = 0.f;
    #pragma unroll
    for (int j = 0; j < 4; j++) {
        v[j] = src[tid + j * 256];
        mx = fmaxf(mx, fmaxf(fmaxf(fabsf(v[j].x), fabsf(v[j].y)),
                             fmaxf(fabsf(v[j].z), fabsf(v[j].w))));
    }
    red[tid] = mx; __syncthreads();
    for (int o = 128; o > 0; o >>= 1) {
        if (tid < o) red[tid] = fmaxf(red[tid], red[tid + o]);
        __syncthreads();
    }
    float rowmax = red[0];
    float inv = (rowmax > 0.f) ? (127.0f / rowmax) : 0.f;
    if (tid == 0) g_sh[entry] = rowmax * (1.0f / 127.0f);
    #pragma unroll
    for (int j = 0; j < 4; j++) {
        int8_t h0, h1, h2, h3, l0, l1, l2, l3;
        quant2(v[j].x, inv, h0, l0); quant2(v[j].y, inv, h1, l1);
        quant2(v[j].z, inv, h2, l2); quant2(v[j].w, inv, h3, l3);
        ((char4*)g_hq_hi)[(size_t)entry * (HH / 4) + tid + j * 256] =
            make_char4(h0, h1, h2, h3);
        ((char4*)g_hq_lo)[(size_t)entry * (HH / 4) + tid + j * 256] =
            make_char4(l0, l1, l2, l3);
    }
}

__global__ void moe_combine_kernel(float* __restrict__ out) {
    int t = blockIdx.x;
    int e0 = g_t2e[2 * t], e1 = g_t2e[2 * t + 1];
    float w0 = g_wts[2 * t], w1 = g_wts[2 * t + 1];
    const float4* y0 = (const float4*)(g_y + (size_t)e0 * DD);
    const float4* y1 = (const float4*)(g_y + (size_t)e1 * DD);
    float4*       o  = (float4*)(out + (size_t)t * DD);
    int i = threadIdx.x;
    float4 a = y0[i], b = y1[i];
    o[i] = make_float4(fmaf(w0, a.x, w1 * b.x), fmaf(w0, a.y, w1 * b.y),
                       fmaf(w0, a.z, w1 * b.z), fmaf(w0, a.w, w1 * b.w));
}

// ------------------------- int8 two-limb GEMM -------------------------
// D = (sa sb) * (Ahi.Bhi + (Ahi.Blo + Alo.Bhi)/128)
// CTA tile 128x128; 8 warps, warp tile 64x32 (2m x 4n). K-chunk 64 (bytes).
// smem: per stage [Ahi|Alo|Bhi|Blo], 128 rows x 64B, stride 80 (ldmatrix CF).
// 4 stages, 1 barrier per chunk, cp.async prefetch c+2.
#define RS   80
#define APL  (128 * RS)        // one plane, bytes
#define STGB (4 * APL)         // stage bytes (40960)
#define NSTG 4

template <int DO_GELU>
__global__ void __launch_bounds__(256, 1)
moe_ffn_i8(const int8_t* __restrict__ Ahi, const int8_t* __restrict__ Alo,
           const float* __restrict__ SA,
           const int8_t* __restrict__ Bhi, const int8_t* __restrict__ Blo,
           const float* __restrict__ SB,
           const float* __restrict__ bias, float* __restrict__ Out,
           int K, int Ntot) {
    int e   = blockIdx.z;
    int cnt = g_cnt[e];
    int m0  = blockIdx.x * 128;
    if (m0 >= cnt) return;
    int base = expert_base(e);
    int n0   = blockIdx.y * 128;

    extern __shared__ __align__(16) char smem[];
    uint32_t sb0 = s2u(smem);
    float* sSb   = (float*)(smem + NSTG * STGB);
    float* sBias = sSb + 128;

    int tid  = threadIdx.x;
    int lane = tid & 31, w = tid >> 5;
    int g = lane >> 2, tg = lane & 3;
    int wm = w & 1, wn = w >> 1;          // 2 m-groups x 4 n-groups

    // ldmatrix lane offsets (matrix = lane>>3, row-in-matrix = lane&7)
    int am = lane >> 3, ar = lane & 7;
    uint32_t aoff = (uint32_t)((wm * 64 + (am & 1) * 8 + ar) * RS + (am >> 1) * 16);
    uint32_t boff = (uint32_t)((wn * 32 + (am >> 1) * 8 + ar) * RS + (am & 1) * 16);

    if (tid < 128) {
        sSb[tid]   = SB[(size_t)e * Ntot + n0 + tid];
        sBias[tid] = bias[(size_t)e * Ntot + n0 + tid];
    }

    const int8_t* Ah = Ahi + (size_t)(base + m0) * K;
    const int8_t* Al = Alo + (size_t)(base + m0) * K;
    const int8_t* Bh = Bhi + ((size_t)e * Ntot + n0) * K;
    const int8_t* Bl = Blo + ((size_t)e * Ntot + n0) * K;
    int C = K >> 6;                        // k-chunk 64

    // per chunk: 4 planes x 128 rows x 4 cp16 = 2048 cp16 -> 8/thread, 4 parts
    auto load_part = [&](int c, int s, int part) {
        int i = tid + (part & 1) * 256;
        int row = i >> 2, seg = i & 3;
        size_t gk = (size_t)c * 64 + seg * 16;
        uint32_t dst = sb0 + (uint32_t)s * STGB + (uint32_t)(row * RS + seg * 16);
        if (part < 2) {
            cp16(dst,               Ah + (size_t)row * K + gk);
            cp16(dst + 2u * APL,    Bh + (size_t)row * K + gk);
        } else {
            cp16(dst + 1u * APL,    Al + (size_t)row * K + gk);
            cp16(dst + 3u * APL,    Bl + (size_t)row * K + gk);
        }
    };
    auto load_full = [&](int c, int s) {
        #pragma unroll
        for (int p = 0; p < 4; p++) load_part(c, s, p);
        asm volatile("cp.async.commit_group;" ::: "memory");
    };

    load_full(0, 0);
    load_full(1, 1);

    int D0[4][4][4], D1[4][4][4];
    #pragma unroll
    for (int mt = 0; mt < 4; mt++)
        #pragma unroll
        for (int nt = 0; nt < 4; nt++)
            #pragma unroll
            for (int q = 0; q < 4; q++) { D0[mt][nt][q] = 0; D1[mt][nt][q] = 0; }

    for (int c = 0; c < C; c++) {
        int s = c & 3;
        if (c + 1 < C) { asm volatile("cp.async.wait_group 1;" ::: "memory"); }
        else           { asm volatile("cp.async.wait_group 0;" ::: "memory"); }
        __syncthreads();

        int sp = (c + 2) & 3;
        bool ld = (c + 2 < C);
        uint32_t stg = sb0 + (uint32_t)s * STGB;

        #pragma unroll
        for (int ks = 0; ks < 2; ks++) {   // two k32 halves of the 64B chunk
            uint32_t ah[4][4], al[4][4], bh[2][4], bl[2][4];
            uint32_t ka = (uint32_t)(ks * 32);
            #pragma unroll
            for (int mt = 0; mt < 4; mt++) {
                ldm4(ah[mt], stg +            aoff + (uint32_t)(mt * 16 * RS) + ka);
                ldm4(al[mt], stg + 1u * APL + aoff + (uint32_t)(mt * 16 * RS) + ka);
            }
            #pragma unroll
            for (int blk = 0; blk < 2; blk++) {
                ldm4(bh[blk], stg + 2u * APL + boff + (uint32_t)(blk * 16 * RS) + ka);
                ldm4(bl[blk], stg + 3u * APL + boff + (uint32_t)(blk * 16 * RS) + ka);
            }
            if (ld) { load_part(c + 2, sp, 2 * ks); load_part(c + 2, sp, 2 * ks + 1); }
            #pragma unroll
            for (int mt = 0; mt < 4; mt++)
                #pragma unroll
                for (int blk = 0; blk < 2; blk++)
                    #pragma unroll
                    for (int q = 0; q < 2; q++) {
                        int nt = blk * 2 + q;
                        imma32(D0[mt][nt], ah[mt], bh[blk][2 * q], bh[blk][2 * q + 1]);
                        imma32(D1[mt][nt], ah[mt], bl[blk][2 * q], bl[blk][2 * q + 1]);
                        imma32(D1[mt][nt], al[mt], bh[blk][2 * q], bh[blk][2 * q + 1]);
                    }
        }
        if (ld) asm volatile("cp.async.commit_group;" ::: "memory");
    }

    // epilogue: val = sa*sb*(D0 + D1/128) + bias (+gelu for FFN1)
    #pragma unroll
    for (int mt = 0; mt < 4; mt++) {
        int r0 = m0 + wm * 64 + mt * 16 + g;
        #pragma unroll
        for (int half = 0; half < 2; half++) {
            int r = r0 + half * 8;
            if (r < cnt) {
                float sa = SA[base + r];
                size_t orow = (size_t)(base + r) * Ntot + n0;
                #pragma unroll
                for (int nt = 0; nt < 4; nt++) {
                    int col = wn * 32 + nt * 8 + 2 * tg;
                    float d00 = (float)D0[mt][nt][half * 2 + 0];
                    float d10 = (float)D1[mt][nt][half * 2 + 0];
                    float d01 = (float)D0[mt][nt][half * 2 + 1];
                    float d11 = (float)D1[mt][nt][half * 2 + 1];
                    float v0 = sa * sSb[col]     * fmaf(d10, 0.0078125f, d00) + sBias[col];
                    float v1 = sa * sSb[col + 1] * fmaf(d11, 0.0078125f, d01) + sBias[col + 1];
                    if (DO_GELU) { v0 = gelu_fast(v0); v1 = gelu_fast(v1); }
                    *(float2*)(Out + orow + col) = make_float2(v0, v1);
                }
            }
        }
    }
}

// ------------------------- launcher -------------------------
extern "C" void kernel_launch(void* const* d_in, const int* in_sizes, int n_in,
                              void* d_out, int out_size) {
    const float* x  = (const float*)d_in[0];
    const float* gw = (const float*)d_in[1];
    const float* gb = (const float*)d_in[2];
    const float* w1 = (const float*)d_in[3];
    const float* b1 = (const float*)d_in[4];
    const float* w2 = (const float*)d_in[5];
    const float* b2 = (const float*)d_in[6];
    float* out = (float*)d_out;

    void *pw1h, *pw1l, *pw2h, *pw2l, *pxh, *pxl, *phh, *phl;
    void *psa, *psh, *psw1, *psw2, *ph, *py;
    cudaGetSymbolAddress(&pw1h, g_w1q_hi); cudaGetSymbolAddress(&pw1l, g_w1q_lo);
    cudaGetSymbolAddress(&pw2h, g_w2q_hi); cudaGetSymbolAddress(&pw2l, g_w2q_lo);
    cudaGetSymbolAddress(&pxh,  g_xq_hi);  cudaGetSymbolAddress(&pxl,  g_xq_lo);
    cudaGetSymbolAddress(&phh,  g_hq_hi);  cudaGetSymbolAddress(&phl,  g_hq_lo);
    cudaGetSymbolAddress(&psa,  g_sa);     cudaGetSymbolAddress(&psh,  g_sh);
    cudaGetSymbolAddress(&psw1, g_sw1);    cudaGetSymbolAddress(&psw2, g_sw2);
    cudaGetSymbolAddress(&ph,   g_h);      cudaGetSymbolAddress(&py,   g_y);

    size_t smem = NSTG * STGB + 256 * sizeof(float) + 64;  // ~165 KB
    cudaFuncSetAttribute(moe_ffn_i8<1>,
                         cudaFuncAttributeMaxDynamicSharedMemorySize, (int)smem);
    cudaFuncSetAttribute(moe_ffn_i8<0>,
                         cudaFuncAttributeMaxDynamicSharedMemorySize, (int)smem);

    moe_reset_kernel<<<1, 32>>>();
    // weight scales + quantize/transpose: w1 [E][D][H] -> [E][H][D] planes
    moe_wscale_kernel<<<dim3(HH / 256, NE), 256>>>(w1, (float*)psw1, DD, HH);
    moe_wscale_kernel<<<dim3(DD / 256, NE), 256>>>(w2, (float*)psw2, HH, DD);
    moe_wquant_kernel<<<dim3(HH / 32, DD / 32, NE), dim3(32, 8)>>>(
        w1, (const float*)psw1, (int8_t*)pw1h, (int8_t*)pw1l, DD, HH);
    moe_wquant_kernel<<<dim3(DD / 32, HH / 32, NE), dim3(32, 8)>>>(
        w2, (const float*)psw2, (int8_t*)pw2h, (int8_t*)pw2l, HH, DD);
    moe_gate_kernel<<<NT / 8, 256>>>(x, gw, gb);
    moe_gatherq_kernel<<<dim3(64, NE), 256>>>(x);
    // FFN1: g_h = gelu(x @ w1 + b1)
    moe_ffn_i8<1><<<dim3(64, HH / 128, NE), 256, smem>>>(
        (const int8_t*)pxh, (const int8_t*)pxl, (const float*)psa,
        (const int8_t*)pw1h, (const int8_t*)pw1l, (const float*)psw1,
        b1, (float*)ph, DD, HH);
    moe_hquant_kernel<<<NENT, 256>>>();
    // FFN2: g_y = h @ w2 + b2
    moe_ffn_i8<0><<<dim3(64, DD / 128, NE), 256, smem>>>(
        (const int8_t*)phh, (const int8_t*)phl, (const float*)psh,
        (const int8_t*)pw2h, (const int8_t*)pw2l, (const float*)psw2,
        b2, (float*)py, HH, DD);
    moe_combine_kernel<<<NT, 256>>>(out);
}

// round 14
// speedup vs baseline: 2.0772x; 2.0772x over previous
#include <cuda_runtime.h>
#include <cuda_fp16.h>
#include <cstdint>

#define NT   8192   // tokens
#define DD   1024   // model dim
#define HH   4096   // hidden dim
#define NE   8      // experts
#define NENT 16384
#define NENT_PAD 16512

// ------------------------- device scratch (no allocs) -------------------------
__device__ __half g_w1h[(size_t)NE * DD * HH];   // fp16(w1), layout [E][D][H]
__device__ __half g_w2h[(size_t)NE * HH * DD];   // fp16(w2), layout [E][H][D]
__device__ __half g_xe16[(size_t)NENT_PAD * DD]; // gathered fp16 inputs per entry
__device__ __half g_h16 [(size_t)NENT_PAD * HH]; // fp16 gelu(x@w1+b1)
__device__ float  g_y  [(size_t)NENT_PAD * DD];  // h@w2+b2 (fp32)
__device__ float  g_wts[NT * 2];
__device__ int    g_list[NE * NT];
__device__ int    g_t2e [NT * 2];
__device__ int    g_cnt [NE];

// ------------------------- helpers -------------------------
__device__ __forceinline__ uint32_t s2u(const void* p) {
    return (uint32_t)__cvta_generic_to_shared(p);
}
__device__ __forceinline__ uint32_t f2h2(float a, float b) {
    __half2 h = __floats2half2_rn(a, b);
    return *reinterpret_cast<uint32_t*>(&h);
}
// gelu(x) = x * sigmoid(2*0.79788456*(x + 0.044715 x^3)); matches tanh-gelu to ~1e-7
__device__ __forceinline__ float gelu_fast(float x) {
    float z = x * fmaf(0.10294324f, x * x, 2.30220822f);  // 2u*log2(e)
    float ex; asm("ex2.approx.f32 %0, %1;" : "=f"(ex) : "f"(-z));
    float r;  asm("rcp.approx.f32 %0, %1;" : "=f"(r)  : "f"(1.0f + ex));
    return x * r;
}
__device__ __forceinline__ void cp16(uint32_t s, const void* g) {
    asm volatile("cp.async.cg.shared.global [%0], [%1], 16;" :: "r"(s), "l"(g));
}
__device__ __forceinline__ void ldm4(uint32_t a[4], uint32_t addr) {
    asm volatile("ldmatrix.sync.aligned.m8n8.x4.shared.b16 {%0,%1,%2,%3}, [%4];"
                 : "=r"(a[0]), "=r"(a[1]), "=r"(a[2]), "=r"(a[3]) : "r"(addr));
}
__device__ __forceinline__ void ldm4t(uint32_t a[4], uint32_t addr) {
    asm volatile("ldmatrix.sync.aligned.m8n8.x4.trans.shared.b16 {%0,%1,%2,%3}, [%4];"
                 : "=r"(a[0]), "=r"(a[1]), "=r"(a[2]), "=r"(a[3]) : "r"(addr));
}
__device__ __forceinline__ void mma16(float d[4], const uint32_t a[4],
                                      uint32_t b0, uint32_t b1) {
    asm volatile(
        "mma.sync.aligned.m16n8k16.row.col.f32.f16.f16.f32 "
        "{%0,%1,%2,%3}, {%4,%5,%6,%7}, {%8,%9}, {%0,%1,%2,%3};"
        : "+f"(d[0]), "+f"(d[1]), "+f"(d[2]), "+f"(d[3])
        : "r"(a[0]), "r"(a[1]), "r"(a[2]), "r"(a[3]), "r"(b0), "r"(b1));
}
__device__ __forceinline__ int expert_base(int e) {
    int b = 0;
    #pragma unroll
    for (int i = 0; i < NE; i++) b += (i < e) ? g_cnt[i] : 0;
    return b;
}

// ------------------------- small kernels -------------------------
__global__ void moe_reset_kernel() {
    if (threadIdx.x < NE) g_cnt[threadIdx.x] = 0;
}

// fp32 -> fp16 elementwise (8 elems/thread), layout unchanged
__global__ void moe_wcvt_kernel(const float4* __restrict__ src,
                                uint4* __restrict__ dst) {
    size_t i = (size_t)blockIdx.x * 256 + threadIdx.x;
    float4 a = src[2 * i], b = src[2 * i + 1];
    uint4 o;
    o.x = f2h2(a.x, a.y); o.y = f2h2(a.z, a.w);
    o.z = f2h2(b.x, b.y); o.w = f2h2(b.z, b.w);
    dst[i] = o;
}

__global__ void moe_gate_kernel(const float* __restrict__ x,
                                const float* __restrict__ gw,
                                const float* __restrict__ gb) {
    int warp = threadIdx.x >> 5, lane = threadIdx.x & 31;
    int t = blockIdx.x * 8 + warp;
    float acc[NE];
    #pragma unroll
    for (int e = 0; e < NE; e++) acc[e] = 0.f;
    const float* xr = x + (size_t)t * DD;
    for (int k = lane; k < DD; k += 32) {
        float xv = xr[k];
        const float4* g4 = (const float4*)(gw + (size_t)k * NE);
        float4 a = g4[0], b = g4[1];
        acc[0] = fmaf(xv, a.x, acc[0]); acc[1] = fmaf(xv, a.y, acc[1]);
        acc[2] = fmaf(xv, a.z, acc[2]); acc[3] = fmaf(xv, a.w, acc[3]);
        acc[4] = fmaf(xv, b.x, acc[4]); acc[5] = fmaf(xv, b.y, acc[5]);
        acc[6] = fmaf(xv, b.z, acc[6]); acc[7] = fmaf(xv, b.w, acc[7]);
    }
    #pragma unroll
    for (int off = 16; off > 0; off >>= 1)
        #pragma unroll
        for (int e = 0; e < NE; e++)
            acc[e] += __shfl_xor_sync(0xFFFFFFFFu, acc[e], off);
    if (lane == 0) {
        float l[NE];
        #pragma unroll
        for (int e = 0; e < NE; e++) l[e] = acc[e] + gb[e];
        int i0 = 0;
        #pragma unroll
        for (int e = 1; e < NE; e++) if (l[e] > l[i0]) i0 = e;
        int i1 = (i0 == 0) ? 1 : 0;
        #pragma unroll
        for (int e = 0; e < NE; e++) if (e != i0 && l[e] > l[i1]) i1 = e;
        float ex = __expf(l[i1] - l[i0]);
        float s  = 1.0f + ex;
        int s0 = atomicAdd(&g_cnt[i0], 1);
        g_list[i0 * NT + s0] = t * 2;
        int s1 = atomicAdd(&g_cnt[i1], 1);
        g_list[i1 * NT + s1] = t * 2 + 1;
        g_wts[t * 2]     = 1.0f / s;
        g_wts[t * 2 + 1] = ex / s;
    }
}

// gather x rows per entry, convert to fp16
__global__ void moe_gather_kernel(const float* __restrict__ x) {
    int e = blockIdx.y;
    int cnt = g_cnt[e], base = expert_base(e);
    int tid = threadIdx.x;
    for (int slot = blockIdx.x; slot < cnt; slot += gridDim.x) {
        int tokj  = g_list[e * NT + slot];
        int entry = base + slot;
        if (tid == 0) g_t2e[tokj] = entry;
        float4 v = ((const float4*)(x + (size_t)(tokj >> 1) * DD))[tid];
        uint2 o = make_uint2(f2h2(v.x, v.y), f2h2(v.z, v.w));
        ((uint2*)(g_xe16 + (size_t)entry * DD))[tid] = o;
    }
}

__global__ void moe_combine_kernel(float* __restrict__ out) {
    int t = blockIdx.x;
    int e0 = g_t2e[2 * t], e1 = g_t2e[2 * t + 1];
    float w0 = g_wts[2 * t], w1 = g_wts[2 * t + 1];
    const float4* y0 = (const float4*)(g_y + (size_t)e0 * DD);
    const float4* y1 = (const float4*)(g_y + (size_t)e1 * DD);
    float4*       o  = (float4*)(out + (size_t)t * DD);
    int i = threadIdx.x;
    float4 a = y0[i], b = y1[i];
    o[i] = make_float4(fmaf(w0, a.x, w1 * b.x), fmaf(w0, a.y, w1 * b.y),
                       fmaf(w0, a.z, w1 * b.z), fmaf(w0, a.w, w1 * b.w));
}

// ------------------------- fp16 mma.sync GEMM -------------------------
// CTA tile 128x256; 8 warps, warp tile 64x64 (2m x 4n); K chunk 64.
// A fp16 [m][k] (k contig), frag via ldmatrix.x4;
// B fp16 [k][n] (n contig), frag via ldmatrix.x4.trans.
// 4-stage cp.async pipeline, 1 barrier/chunk, prefetch c+2.
#define SA_H 72                     // A row stride, halves (CF: banks 4r)
#define SB_H 264                    // B row stride, halves (CF: banks 4k)
#define A_ST (128 * SA_H * 2)       // 18432 B
#define B_ST (64 * SB_H * 2)        // 33792 B
#define STG_B (A_ST + B_ST)         // 52224 B
#define NSTG 4

template <int DO_GELU>
__global__ void __launch_bounds__(256, 1)
moe_ffn_h(const __half* __restrict__ A, const __half* __restrict__ B,
          const float* __restrict__ bias, void* __restrict__ OutV,
          int K, int Ntot) {
    int e   = blockIdx.z;
    int cnt = g_cnt[e];
    int m0  = blockIdx.x * 128;
    if (m0 >= cnt) return;
    int base = expert_base(e);
    int n0   = blockIdx.y * 256;

    extern __shared__ __align__(16) char smem[];
    uint32_t sb = s2u(smem);
    float* sBias = (float*)(smem + NSTG * STG_B);

    int tid  = threadIdx.x;
    int lane = tid & 31, w = tid >> 5;
    int g = lane >> 2, tg = lane & 3;
    int wm = w & 1, wn = w >> 1;

    // A ldmatrix lane address: rows {m0-7|m8-15} x k-halves {0|8}
    uint32_t aLane = (uint32_t)(((wm * 64 + (lane & 7) + ((lane >> 3) & 1) * 8) * SA_H
                                 + ((lane >> 4) & 1) * 8) * 2);
    // B trans-ldmatrix lane address: rows k {0-7|8-15}, n-offset {0|8}
    uint32_t bLane = (uint32_t)((((lane & 7) + ((lane >> 3) & 1) * 8) * SB_H
                                 + ((lane >> 4) & 1) * 8 + wn * 64) * 2);

    sBias[tid] = bias[(size_t)e * Ntot + n0 + tid];

    const __half* Ab = A + (size_t)(base + m0) * K;
    const __half* Bb = B + (size_t)e * K * Ntot + n0;
    int C = K >> 6;

    // per chunk: A 1024 cp16 (4/thr), B 2048 cp16 (8/thr)
    auto load_part = [&](int c, int s, int part) {  // parts 0..3, 3 cp16 each
        {
            int i = tid + part * 256;
            int m = i >> 3, seg = i & 7;
            cp16(sb + (uint32_t)s * STG_B + (uint32_t)((m * SA_H + seg * 8) * 2),
                 Ab + (size_t)m * K + c * 64 + seg * 8);
        }
        #pragma unroll
        for (int jj = 0; jj < 2; jj++) {
            int i = tid + (part * 2 + jj) * 256;
            int k = i >> 5, seg = i & 31;
            cp16(sb + (uint32_t)s * STG_B + A_ST + (uint32_t)((k * SB_H + seg * 8) * 2),
                 Bb + (size_t)(c * 64 + k) * Ntot + seg * 8);
        }
    };
    auto load_full = [&](int c, int s) {
        #pragma unroll
        for (int p = 0; p < 4; p++) load_part(c, s, p);
        asm volatile("cp.async.commit_group;" ::: "memory");
    };

    load_full(0, 0);
    load_full(1, 1);

    float acc[4][8][4];
    #pragma unroll
    for (int mt = 0; mt < 4; mt++)
        #pragma unroll
        for (int nt = 0; nt < 8; nt++)
            #pragma unroll
            for (int q = 0; q < 4; q++) acc[mt][nt][q] = 0.f;

    for (int c = 0; c < C; c++) {
        int s = c & 3;
        if (c + 1 < C) { asm volatile("cp.async.wait_group 1;" ::: "memory"); }
        else           { asm volatile("cp.async.wait_group 0;" ::: "memory"); }
        __syncthreads();

        int sp = (c + 2) & 3;
        bool ld = (c + 2 < C);
        uint32_t stgA = sb + (uint32_t)s * STG_B;
        uint32_t stgB = stgA + A_ST;

        #pragma unroll
        for (int ks = 0; ks < 4; ks++) {     // four k16 steps of the k64 chunk
            uint32_t af[4][4], bf[4][4];
            uint32_t ka = (uint32_t)(ks * 32);              // 16 halves
            uint32_t kb = (uint32_t)(ks * 16 * SB_H * 2);   // 16 k-rows
            #pragma unroll
            for (int mt = 0; mt < 4; mt++)
                ldm4(af[mt], stgA + aLane + (uint32_t)(mt * 16 * SA_H * 2) + ka);
            #pragma unroll
            for (int nb = 0; nb < 4; nb++)   // n16 groups within warp n64
                ldm4t(bf[nb], stgB + bLane + kb + (uint32_t)(nb * 32));
            if (ld) load_part(c + 2, sp, ks);
            #pragma unroll
            for (int mt = 0; mt < 4; mt++)
                #pragma unroll
                for (int nt = 0; nt < 8; nt++) {
                    int p = nt >> 1, q = (nt & 1) * 2;
                    mma16(acc[mt][nt], af[mt], bf[p][q], bf[p][q + 1]);
                }
        }
        if (ld) asm volatile("cp.async.commit_group;" ::: "memory");
    }

    // epilogue: bias (+gelu for FFN1); FFN1 writes fp16, FFN2 writes fp32
    #pragma unroll
    for (int mt = 0; mt < 4; mt++) {
        int r0 = m0 + wm * 64 + mt * 16 + g;
        #pragma unroll
        for (int half = 0; half < 2; half++) {
            int r = r0 + half * 8;
            if (r < cnt) {
                size_t orow = (size_t)(base + r) * Ntot + n0;
                #pragma unroll
                for (int nt = 0; nt < 8; nt++) {
                    int col = wn * 64 + nt * 8 + 2 * tg;
                    float v0 = acc[mt][nt][half * 2 + 0] + sBias[col];
                    float v1 = acc[mt][nt][half * 2 + 1] + sBias[col + 1];
                    if (DO_GELU) {
                        v0 = gelu_fast(v0); v1 = gelu_fast(v1);
                        uint32_t hv = f2h2(v0, v1);
                        *(uint32_t*)((__half*)OutV + orow + col) = hv;
                    } else {
                        *(float2*)((float*)OutV + orow + col) = make_float2(v0, v1);
                    }
                }
            }
        }
    }
}

// ------------------------- launcher -------------------------
extern "C" void kernel_launch(void* const* d_in, const int* in_sizes, int n_in,
                              void* d_out, int out_size) {
    const float* x  = (const float*)d_in[0];
    const float* gw = (const float*)d_in[1];
    const float* gb = (const float*)d_in[2];
    const float* w1 = (const float*)d_in[3];
    const float* b1 = (const float*)d_in[4];
    const float* w2 = (const float*)d_in[5];
    const float* b2 = (const float*)d_in[6];
    float* out = (float*)d_out;

    void *pw1, *pw2, *pxe, *ph, *py;
    cudaGetSymbolAddress(&pw1, g_w1h);
    cudaGetSymbolAddress(&pw2, g_w2h);
    cudaGetSymbolAddress(&pxe, g_xe16);
    cudaGetSymbolAddress(&ph,  g_h16);
    cudaGetSymbolAddress(&py,  g_y);

    size_t smem = NSTG * STG_B + 256 * sizeof(float) + 64;  // ~205 KB
    cudaFuncSetAttribute(moe_ffn_h<1>,
                         cudaFuncAttributeMaxDynamicSharedMemorySize, (int)smem);
    cudaFuncSetAttribute(moe_ffn_h<0>,
                         cudaFuncAttributeMaxDynamicSharedMemorySize, (int)smem);

    moe_reset_kernel<<<1, 32>>>();
    // weights -> fp16, layout unchanged ([k][n], n contig)
    moe_wcvt_kernel<<<(int)((size_t)NE * DD * HH / 8 / 256), 256>>>(
        (const float4*)w1, (uint4*)pw1);
    moe_wcvt_kernel<<<(int)((size_t)NE * HH * DD / 8 / 256), 256>>>(
        (const float4*)w2, (uint4*)pw2);
    moe_gate_kernel<<<NT / 8, 256>>>(x, gw, gb);
    moe_gather_kernel<<<dim3(64, NE), 256>>>(x);
    // FFN1: g_h16 = fp16(gelu(x @ w1 + b1))
    moe_ffn_h<1><<<dim3(64, HH / 256, NE), 256, smem>>>(
        (const __half*)pxe, (const __half*)pw1, b1, ph, DD, HH);
    // FFN2: g_y = h @ w2 + b2
    moe_ffn_h<0><<<dim3(64, DD / 256, NE), 256, smem>>>(
        (const __half*)ph, (const __half*)pw2, b2, py, HH, DD);
    moe_combine_kernel<<<NT, 256>>>(out);
}

// round 15
// speedup vs baseline: 2.1017x; 1.0118x over previous
#include <cuda_runtime.h>
#include <cuda_fp16.h>
#include <cstdint>

#define NT   8192   // tokens
#define DD   1024   // model dim
#define HH   4096   // hidden dim
#define NE   8      // experts
#define NENT 16384
#define NENT_PAD 16512

// ------------------------- device scratch (no allocs) -------------------------
__device__ __half g_w1h[(size_t)NE * DD * HH];   // fp16(w1), layout [E][D][H]
__device__ __half g_w2h[(size_t)NE * HH * DD];   // fp16(w2), layout [E][H][D]
__device__ __half g_xe16[(size_t)NENT_PAD * DD]; // gathered fp16 inputs per entry
__device__ __half g_h16 [(size_t)NENT_PAD * HH]; // fp16 gelu(x@w1+b1)
__device__ float  g_y  [(size_t)NENT_PAD * DD];  // h@w2+b2 (fp32)
__device__ float  g_wts[NT * 2];
__device__ int    g_list[NE * NT];
__device__ int    g_t2e [NT * 2];
__device__ int    g_cnt [NE];

// ------------------------- helpers -------------------------
__device__ __forceinline__ uint32_t s2u(const void* p) {
    return (uint32_t)__cvta_generic_to_shared(p);
}
__device__ __forceinline__ uint32_t f2h2(float a, float b) {
    __half2 h = __floats2half2_rn(a, b);
    return *reinterpret_cast<uint32_t*>(&h);
}
// gelu(x) = x * sigmoid(2*0.79788456*(x + 0.044715 x^3)); matches tanh-gelu to ~1e-7
__device__ __forceinline__ float gelu_fast(float x) {
    float z = x * fmaf(0.10294324f, x * x, 2.30220822f);  // 2u*log2(e)
    float ex; asm("ex2.approx.f32 %0, %1;" : "=f"(ex) : "f"(-z));
    float r;  asm("rcp.approx.f32 %0, %1;" : "=f"(r)  : "f"(1.0f + ex));
    return x * r;
}
__device__ __forceinline__ void cp16(uint32_t s, const void* g) {
    asm volatile("cp.async.cg.shared.global [%0], [%1], 16;" :: "r"(s), "l"(g));
}
__device__ __forceinline__ void ldm4(uint32_t a[4], uint32_t addr) {
    asm volatile("ldmatrix.sync.aligned.m8n8.x4.shared.b16 {%0,%1,%2,%3}, [%4];"
                 : "=r"(a[0]), "=r"(a[1]), "=r"(a[2]), "=r"(a[3]) : "r"(addr));
}
__device__ __forceinline__ void ldm4t(uint32_t a[4], uint32_t addr) {
    asm volatile("ldmatrix.sync.aligned.m8n8.x4.trans.shared.b16 {%0,%1,%2,%3}, [%4];"
                 : "=r"(a[0]), "=r"(a[1]), "=r"(a[2]), "=r"(a[3]) : "r"(addr));
}
__device__ __forceinline__ void mma16(float d[4], const uint32_t a[4],
                                      uint32_t b0, uint32_t b1) {
    asm volatile(
        "mma.sync.aligned.m16n8k16.row.col.f32.f16.f16.f32 "
        "{%0,%1,%2,%3}, {%4,%5,%6,%7}, {%8,%9}, {%0,%1,%2,%3};"
        : "+f"(d[0]), "+f"(d[1]), "+f"(d[2]), "+f"(d[3])
        : "r"(a[0]), "r"(a[1]), "r"(a[2]), "r"(a[3]), "r"(b0), "r"(b1));
}
__device__ __forceinline__ int expert_base(int e) {
    int b = 0;
    #pragma unroll
    for (int i = 0; i < NE; i++) b += (i < e) ? g_cnt[i] : 0;
    return b;
}

// ------------------------- small kernels -------------------------
__global__ void moe_reset_kernel() {
    if (threadIdx.x < NE) g_cnt[threadIdx.x] = 0;
}

// fp32 -> fp16 elementwise (8 elems/thread), layout unchanged
__global__ void moe_wcvt_kernel(const float4* __restrict__ src,
                                uint4* __restrict__ dst) {
    size_t i = (size_t)blockIdx.x * 256 + threadIdx.x;
    float4 a = src[2 * i], b = src[2 * i + 1];
    uint4 o;
    o.x = f2h2(a.x, a.y); o.y = f2h2(a.z, a.w);
    o.z = f2h2(b.x, b.y); o.w = f2h2(b.z, b.w);
    dst[i] = o;
}

__global__ void moe_gate_kernel(const float* __restrict__ x,
                                const float* __restrict__ gw,
                                const float* __restrict__ gb) {
    int warp = threadIdx.x >> 5, lane = threadIdx.x & 31;
    int t = blockIdx.x * 8 + warp;
    float acc[NE];
    #pragma unroll
    for (int e = 0; e < NE; e++) acc[e] = 0.f;
    const float* xr = x + (size_t)t * DD;
    for (int k = lane; k < DD; k += 32) {
        float xv = xr[k];
        const float4* g4 = (const float4*)(gw + (size_t)k * NE);
        float4 a = g4[0], b = g4[1];
        acc[0] = fmaf(xv, a.x, acc[0]); acc[1] = fmaf(xv, a.y, acc[1]);
        acc[2] = fmaf(xv, a.z, acc[2]); acc[3] = fmaf(xv, a.w, acc[3]);
        acc[4] = fmaf(xv, b.x, acc[4]); acc[5] = fmaf(xv, b.y, acc[5]);
        acc[6] = fmaf(xv, b.z, acc[6]); acc[7] = fmaf(xv, b.w, acc[7]);
    }
    #pragma unroll
    for (int off = 16; off > 0; off >>= 1)
        #pragma unroll
        for (int e = 0; e < NE; e++)
            acc[e] += __shfl_xor_sync(0xFFFFFFFFu, acc[e], off);
    if (lane == 0) {
        float l[NE];
        #pragma unroll
        for (int e = 0; e < NE; e++) l[e] = acc[e] + gb[e];
        int i0 = 0;
        #pragma unroll
        for (int e = 1; e < NE; e++) if (l[e] > l[i0]) i0 = e;
        int i1 = (i0 == 0) ? 1 : 0;
        #pragma unroll
        for (int e = 0; e < NE; e++) if (e != i0 && l[e] > l[i1]) i1 = e;
        float ex = __expf(l[i1] - l[i0]);
        float s  = 1.0f + ex;
        int s0 = atomicAdd(&g_cnt[i0], 1);
        g_list[i0 * NT + s0] = t * 2;
        int s1 = atomicAdd(&g_cnt[i1], 1);
        g_list[i1 * NT + s1] = t * 2 + 1;
        g_wts[t * 2]     = 1.0f / s;
        g_wts[t * 2 + 1] = ex / s;
    }
}

// gather x rows per entry, convert to fp16
__global__ void moe_gather_kernel(const float* __restrict__ x) {
    int e = blockIdx.y;
    int cnt = g_cnt[e], base = expert_base(e);
    int tid = threadIdx.x;
    for (int slot = blockIdx.x; slot < cnt; slot += gridDim.x) {
        int tokj  = g_list[e * NT + slot];
        int entry = base + slot;
        if (tid == 0) g_t2e[tokj] = entry;
        float4 v = ((const float4*)(x + (size_t)(tokj >> 1) * DD))[tid];
        uint2 o = make_uint2(f2h2(v.x, v.y), f2h2(v.z, v.w));
        ((uint2*)(g_xe16 + (size_t)entry * DD))[tid] = o;
    }
}

__global__ void moe_combine_kernel(float* __restrict__ out) {
    int t = blockIdx.x;
    int e0 = g_t2e[2 * t], e1 = g_t2e[2 * t + 1];
    float w0 = g_wts[2 * t], w1 = g_wts[2 * t + 1];
    const float4* y0 = (const float4*)(g_y + (size_t)e0 * DD);
    const float4* y1 = (const float4*)(g_y + (size_t)e1 * DD);
    float4*       o  = (float4*)(out + (size_t)t * DD);
    int i = threadIdx.x;
    float4 a = y0[i], b = y1[i];
    o[i] = make_float4(fmaf(w0, a.x, w1 * b.x), fmaf(w0, a.y, w1 * b.y),
                       fmaf(w0, a.z, w1 * b.z), fmaf(w0, a.w, w1 * b.w));
}

// ------------------------- fp16 mma.sync GEMM -------------------------
// CTA tile 128x256; 8 warps, warp tile 64x64 (2m x 4n); K chunk 64.
// A fp16 [m][k] via ldmatrix.x4; B fp16 [k][n] via ldmatrix.x4.trans.
// 4-stage cp.async, 2-chunk groups: ONE wait+barrier per 2 chunks.
// Register double-buffered fragments, in-group tail prefetch.
#define SA_H 72                     // A row stride, halves
#define SB_H 264                    // B row stride, halves
#define A_ST (128 * SA_H * 2)       // 18432 B
#define B_ST (64 * SB_H * 2)        // 33792 B
#define STG_B (A_ST + B_ST)         // 52224 B
#define NSTG 4

template <int DO_GELU>
__global__ void __launch_bounds__(256, 1)
moe_ffn_h(const __half* __restrict__ A, const __half* __restrict__ B,
          const float* __restrict__ bias, void* __restrict__ OutV,
          int K, int Ntot) {
    int e   = blockIdx.z;
    int cnt = g_cnt[e];
    int m0  = blockIdx.x * 128;
    if (m0 >= cnt) return;
    int base = expert_base(e);
    int n0   = blockIdx.y * 256;

    extern __shared__ __align__(16) char smem[];
    uint32_t sb = s2u(smem);
    float* sBias = (float*)(smem + NSTG * STG_B);

    int tid  = threadIdx.x;
    int lane = tid & 31, w = tid >> 5;
    int g = lane >> 2, tg = lane & 3;
    int wm = w & 1, wn = w >> 1;

    uint32_t aLane = (uint32_t)(((wm * 64 + (lane & 7) + ((lane >> 3) & 1) * 8) * SA_H
                                 + ((lane >> 4) & 1) * 8) * 2);
    uint32_t bLane = (uint32_t)((((lane & 7) + ((lane >> 3) & 1) * 8) * SB_H
                                 + ((lane >> 4) & 1) * 8 + wn * 64) * 2);

    sBias[tid] = bias[(size_t)e * Ntot + n0 + tid];

    const __half* Ab = A + (size_t)(base + m0) * K;
    const __half* Bb = B + (size_t)e * K * Ntot + n0;
    int C = K >> 6;
    int G = C >> 1;                  // 2-chunk groups; C even (16 or 64)

    auto load_part = [&](int c, int s, int part) {  // parts 0..3, 3 cp16 each
        {
            int i = tid + part * 256;
            int m = i >> 3, seg = i & 7;
            cp16(sb + (uint32_t)s * STG_B + (uint32_t)((m * SA_H + seg * 8) * 2),
                 Ab + (size_t)m * K + c * 64 + seg * 8);
        }
        #pragma unroll
        for (int jj = 0; jj < 2; jj++) {
            int i = tid + (part * 2 + jj) * 256;
            int k = i >> 5, seg = i & 31;
            cp16(sb + (uint32_t)s * STG_B + A_ST + (uint32_t)((k * SB_H + seg * 8) * 2),
                 Bb + (size_t)(c * 64 + k) * Ntot + seg * 8);
        }
    };
    auto load_full = [&](int c, int s) {
        #pragma unroll
        for (int p = 0; p < 4; p++) load_part(c, s, p);
    };

    auto ldfragA = [&](uint32_t af[4][4], int s, int ks) {
        uint32_t stgA = sb + (uint32_t)s * STG_B + aLane + (uint32_t)(ks * 32);
        #pragma unroll
        for (int mt = 0; mt < 4; mt++)
            ldm4(af[mt], stgA + (uint32_t)(mt * 16 * SA_H * 2));
    };
    auto ldfragB = [&](uint32_t bf[4][4], int s, int ks) {
        uint32_t stgB = sb + (uint32_t)s * STG_B + A_ST + bLane
                      + (uint32_t)(ks * 16 * SB_H * 2);
        #pragma unroll
        for (int nb = 0; nb < 4; nb++)
            ldm4t(bf[nb], stgB + (uint32_t)(nb * 32));
    };

    // preload groups 0 and 1 (chunks 0..3 -> stages 0..3), one commit per group
    load_full(0, 0); load_full(1, 1);
    asm volatile("cp.async.commit_group;" ::: "memory");
    load_full(2, 2); load_full(3, 3);
    asm volatile("cp.async.commit_group;" ::: "memory");

    float acc[4][8][4];
    #pragma unroll
    for (int mt = 0; mt < 4; mt++)
        #pragma unroll
        for (int nt = 0; nt < 8; nt++)
            #pragma unroll
            for (int q = 0; q < 4; q++) acc[mt][nt][q] = 0.f;

    uint32_t af[2][4][4], bf[2][4][4];

    for (int j = 0; j < G; j++) {
        int s0 = (2 * j) & 3, s1 = s0 + 1;
        if (j == 0) { asm volatile("cp.async.wait_group 1;" ::: "memory"); }
        else        { asm volatile("cp.async.wait_group 0;" ::: "memory"); }
        __syncthreads();

        ldfragA(af[0], s0, 0); ldfragB(bf[0], s0, 0);

        bool ld = (j >= 1) && (j + 1 < G);   // group j+1 -> group j-1's stages
        int t0 = (s0 + 2) & 3, t1 = t0 + 1;

        // ---- chunk a = 2j (stage s0); front-load next group's slices ----
        #pragma unroll
        for (int ks = 0; ks < 4; ks++) {
            int cur = ks & 1;
            if (ks < 3) { ldfragA(af[cur ^ 1], s0, ks + 1); ldfragB(bf[cur ^ 1], s0, ks + 1); }
            else        { ldfragA(af[cur ^ 1], s1, 0);      ldfragB(bf[cur ^ 1], s1, 0); }
            if (ld) { load_part(2 * j + 2, t0, ks); load_part(2 * j + 3, t1, ks); }
            #pragma unroll
            for (int mt = 0; mt < 4; mt++)
                #pragma unroll
                for (int nt = 0; nt < 8; nt++) {
                    int p = nt >> 1, q = (nt & 1) * 2;
                    mma16(acc[mt][nt], af[cur][mt], bf[cur][p][q], bf[cur][p][q + 1]);
                }
        }
        if (ld) asm volatile("cp.async.commit_group;" ::: "memory");

        // ---- chunk b = 2j+1 (stage s1) ----
        #pragma unroll
        for (int ks = 0; ks < 4; ks++) {
            int cur = ks & 1;
            if (ks < 3) { ldfragA(af[cur ^ 1], s1, ks + 1); ldfragB(bf[cur ^ 1], s1, ks + 1); }
            #pragma unroll
            for (int mt = 0; mt < 4; mt++)
                #pragma unroll
                for (int nt = 0; nt < 8; nt++) {
                    int p = nt >> 1, q = (nt & 1) * 2;
                    mma16(acc[mt][nt], af[cur][mt], bf[cur][p][q], bf[cur][p][q + 1]);
                }
        }
    }

    // epilogue: bias (+gelu for FFN1); FFN1 writes fp16, FFN2 writes fp32
    #pragma unroll
    for (int mt = 0; mt < 4; mt++) {
        int r0 = m0 + wm * 64 + mt * 16 + g;
        #pragma unroll
        for (int half = 0; half < 2; half++) {
            int r = r0 + half * 8;
            if (r < cnt) {
                size_t orow = (size_t)(base + r) * Ntot + n0;
                #pragma unroll
                for (int nt = 0; nt < 8; nt++) {
                    int col = wn * 64 + nt * 8 + 2 * tg;
                    float v0 = acc[mt][nt][half * 2 + 0] + sBias[col];
                    float v1 = acc[mt][nt][half * 2 + 1] + sBias[col + 1];
                    if (DO_GELU) {
                        v0 = gelu_fast(v0); v1 = gelu_fast(v1);
                        uint32_t hv = f2h2(v0, v1);
                        *(uint32_t*)((__half*)OutV + orow + col) = hv;
                    } else {
                        *(float2*)((float*)OutV + orow + col) = make_float2(v0, v1);
                    }
                }
            }
        }
    }
}

// ------------------------- launcher -------------------------
extern "C" void kernel_launch(void* const* d_in, const int* in_sizes, int n_in,
                              void* d_out, int out_size) {
    const float* x  = (const float*)d_in[0];
    const float* gw = (const float*)d_in[1];
    const float* gb = (const float*)d_in[2];
    const float* w1 = (const float*)d_in[3];
    const float* b1 = (const float*)d_in[4];
    const float* w2 = (const float*)d_in[5];
    const float* b2 = (const float*)d_in[6];
    float* out = (float*)d_out;

    void *pw1, *pw2, *pxe, *ph, *py;
    cudaGetSymbolAddress(&pw1, g_w1h);
    cudaGetSymbolAddress(&pw2, g_w2h);
    cudaGetSymbolAddress(&pxe, g_xe16);
    cudaGetSymbolAddress(&ph,  g_h16);
    cudaGetSymbolAddress(&py,  g_y);

    size_t smem = NSTG * STG_B + 256 * sizeof(float) + 64;  // ~205 KB
    cudaFuncSetAttribute(moe_ffn_h<1>,
                         cudaFuncAttributeMaxDynamicSharedMemorySize, (int)smem);
    cudaFuncSetAttribute(moe_ffn_h<0>,
                         cudaFuncAttributeMaxDynamicSharedMemorySize, (int)smem);

    moe_reset_kernel<<<1, 32>>>();
    // weights -> fp16, layout unchanged ([k][n], n contig)
    moe_wcvt_kernel<<<(int)((size_t)NE * DD * HH / 8 / 256), 256>>>(
        (const float4*)w1, (uint4*)pw1);
    moe_wcvt_kernel<<<(int)((size_t)NE * HH * DD / 8 / 256), 256>>>(
        (const float4*)w2, (uint4*)pw2);
    moe_gate_kernel<<<NT / 8, 256>>>(x, gw, gb);
    moe_gather_kernel<<<dim3(64, NE), 256>>>(x);
    // FFN1: g_h16 = fp16(gelu(x @ w1 + b1))
    moe_ffn_h<1><<<dim3(64, HH / 256, NE), 256, smem>>>(
        (const __half*)pxe, (const __half*)pw1, b1, ph, DD, HH);
    // FFN2: g_y = h @ w2 + b2
    moe_ffn_h<0><<<dim3(64, DD / 256, NE), 256, smem>>>(
        (const __half*)ph, (const __half*)pw2, b2, py, HH, DD);
    moe_combine_kernel<<<NT, 256>>>(out);
}

// round 16
// speedup vs baseline: 2.1282x; 1.0126x over previous
#include <cuda_runtime.h>
#include <cuda_fp16.h>
#include <cstdint>

#define NT   8192   // tokens
#define DD   1024   // model dim
#define HH   4096   // hidden dim
#define NE   8      // experts
#define NENT 16384
#define NENT_PAD 16512
#define MAXMT 144   // max m-tiles: sum ceil(cnt_e/128) <= 128+8

// ------------------------- device scratch (no allocs) -------------------------
__device__ __half g_w1h[(size_t)NE * DD * HH];   // fp16(w1), layout [E][D][H]
__device__ __half g_w2h[(size_t)NE * HH * DD];   // fp16(w2), layout [E][H][D]
__device__ __half g_xe16[(size_t)NENT_PAD * DD]; // gathered fp16 inputs per entry
__device__ __half g_h16 [(size_t)NENT_PAD * HH]; // fp16 gelu(x@w1+b1)
__device__ float  g_y  [(size_t)NENT_PAD * DD];  // h@w2+b2 (fp32)
__device__ float  g_wts[NT * 2];
__device__ int    g_list[NE * NT];
__device__ int    g_t2e [NT * 2];
__device__ int    g_cnt [NE];
__device__ int    g_base[NE];
__device__ int    g_map [MAXMT];                 // (e<<16) | m_tile
__device__ int    g_nmt;

// ------------------------- helpers -------------------------
__device__ __forceinline__ uint32_t s2u(const void* p) {
    return (uint32_t)__cvta_generic_to_shared(p);
}
__device__ __forceinline__ uint32_t f2h2(float a, float b) {
    __half2 h = __floats2half2_rn(a, b);
    return *reinterpret_cast<uint32_t*>(&h);
}
// gelu(x) = x * sigmoid(2*0.79788456*(x + 0.044715 x^3)); matches tanh-gelu to ~1e-7
__device__ __forceinline__ float gelu_fast(float x) {
    float z = x * fmaf(0.10294324f, x * x, 2.30220822f);  // 2u*log2(e)
    float ex; asm("ex2.approx.f32 %0, %1;" : "=f"(ex) : "f"(-z));
    float r;  asm("rcp.approx.f32 %0, %1;" : "=f"(r)  : "f"(1.0f + ex));
    return x * r;
}
__device__ __forceinline__ void cp16(uint32_t s, const void* g) {
    asm volatile("cp.async.cg.shared.global [%0], [%1], 16;" :: "r"(s), "l"(g));
}
__device__ __forceinline__ void ldm4(uint32_t a[4], uint32_t addr) {
    asm volatile("ldmatrix.sync.aligned.m8n8.x4.shared.b16 {%0,%1,%2,%3}, [%4];"
                 : "=r"(a[0]), "=r"(a[1]), "=r"(a[2]), "=r"(a[3]) : "r"(addr));
}
__device__ __forceinline__ void ldm4t(uint32_t a[4], uint32_t addr) {
    asm volatile("ldmatrix.sync.aligned.m8n8.x4.trans.shared.b16 {%0,%1,%2,%3}, [%4];"
                 : "=r"(a[0]), "=r"(a[1]), "=r"(a[2]), "=r"(a[3]) : "r"(addr));
}
__device__ __forceinline__ void mma16(float d[4], const uint32_t a[4],
                                      uint32_t b0, uint32_t b1) {
    asm volatile(
        "mma.sync.aligned.m16n8k16.row.col.f32.f16.f16.f32 "
        "{%0,%1,%2,%3}, {%4,%5,%6,%7}, {%8,%9}, {%0,%1,%2,%3};"
        : "+f"(d[0]), "+f"(d[1]), "+f"(d[2]), "+f"(d[3])
        : "r"(a[0]), "r"(a[1]), "r"(a[2]), "r"(a[3]), "r"(b0), "r"(b1));
}

// ------------------------- small kernels -------------------------
__global__ void moe_reset_kernel() {
    if (threadIdx.x < NE) g_cnt[threadIdx.x] = 0;
}

// Fused prepass: gate (blocks 0..1023) + w1->fp16 (next 16384) + w2->fp16.
#define GATE_BLKS 1024
#define WCVT_BLKS 16384
__global__ void moe_prep_kernel(const float* __restrict__ x,
                                const float* __restrict__ gw,
                                const float* __restrict__ gb,
                                const float4* __restrict__ w1,
                                uint4* __restrict__ w1h,
                                const float4* __restrict__ w2,
                                uint4* __restrict__ w2h) {
    int bx = blockIdx.x;
    if (bx >= GATE_BLKS) {
        // weight fp32 -> fp16, 8 elems/thread, layout unchanged
        const float4* src; uint4* dst; size_t i;
        if (bx < GATE_BLKS + WCVT_BLKS) {
            src = w1; dst = w1h;
            i = (size_t)(bx - GATE_BLKS) * 256 + threadIdx.x;
        } else {
            src = w2; dst = w2h;
            i = (size_t)(bx - GATE_BLKS - WCVT_BLKS) * 256 + threadIdx.x;
        }
        float4 a = src[2 * i], b = src[2 * i + 1];
        uint4 o;
        o.x = f2h2(a.x, a.y); o.y = f2h2(a.z, a.w);
        o.z = f2h2(b.x, b.y); o.w = f2h2(b.z, b.w);
        dst[i] = o;
        return;
    }
    // ---- gate ----
    int warp = threadIdx.x >> 5, lane = threadIdx.x & 31;
    int t = bx * 8 + warp;
    float acc[NE];
    #pragma unroll
    for (int e = 0; e < NE; e++) acc[e] = 0.f;
    const float* xr = x + (size_t)t * DD;
    for (int k = lane; k < DD; k += 32) {
        float xv = xr[k];
        const float4* g4 = (const float4*)(gw + (size_t)k * NE);
        float4 a = g4[0], b = g4[1];
        acc[0] = fmaf(xv, a.x, acc[0]); acc[1] = fmaf(xv, a.y, acc[1]);
        acc[2] = fmaf(xv, a.z, acc[2]); acc[3] = fmaf(xv, a.w, acc[3]);
        acc[4] = fmaf(xv, b.x, acc[4]); acc[5] = fmaf(xv, b.y, acc[5]);
        acc[6] = fmaf(xv, b.z, acc[6]); acc[7] = fmaf(xv, b.w, acc[7]);
    }
    #pragma unroll
    for (int off = 16; off > 0; off >>= 1)
        #pragma unroll
        for (int e = 0; e < NE; e++)
            acc[e] += __shfl_xor_sync(0xFFFFFFFFu, acc[e], off);
    if (lane == 0) {
        float l[NE];
        #pragma unroll
        for (int e = 0; e < NE; e++) l[e] = acc[e] + gb[e];
        int i0 = 0;
        #pragma unroll
        for (int e = 1; e < NE; e++) if (l[e] > l[i0]) i0 = e;
        int i1 = (i0 == 0) ? 1 : 0;
        #pragma unroll
        for (int e = 0; e < NE; e++) if (e != i0 && l[e] > l[i1]) i1 = e;
        float ex = __expf(l[i1] - l[i0]);
        float s  = 1.0f + ex;
        int s0 = atomicAdd(&g_cnt[i0], 1);
        g_list[i0 * NT + s0] = t * 2;
        int s1 = atomicAdd(&g_cnt[i1], 1);
        g_list[i1 * NT + s1] = t * 2 + 1;
        g_wts[t * 2]     = 1.0f / s;
        g_wts[t * 2 + 1] = ex / s;
    }
}

// builds prefix bases + compact m-tile map
__global__ void moe_tilemap_kernel() {
    if (threadIdx.x == 0) {
        int b = 0, idx = 0;
        #pragma unroll
        for (int e = 0; e < NE; e++) {
            g_base[e] = b;
            int cnt = g_cnt[e];
            b += cnt;
            for (int m = 0; m * 128 < cnt; m++) g_map[idx++] = (e << 16) | m;
        }
        g_nmt = idx;
    }
}

// gather x rows per entry, convert to fp16
__global__ void moe_gather_kernel(const float* __restrict__ x) {
    int e = blockIdx.y;
    int cnt = g_cnt[e], base = g_base[e];
    int tid = threadIdx.x;
    for (int slot = blockIdx.x; slot < cnt; slot += gridDim.x) {
        int tokj  = g_list[e * NT + slot];
        int entry = base + slot;
        if (tid == 0) g_t2e[tokj] = entry;
        float4 v = ((const float4*)(x + (size_t)(tokj >> 1) * DD))[tid];
        uint2 o = make_uint2(f2h2(v.x, v.y), f2h2(v.z, v.w));
        ((uint2*)(g_xe16 + (size_t)entry * DD))[tid] = o;
    }
}

__global__ void moe_combine_kernel(float* __restrict__ out) {
    int t = blockIdx.x;
    int e0 = g_t2e[2 * t], e1 = g_t2e[2 * t + 1];
    float w0 = g_wts[2 * t], w1 = g_wts[2 * t + 1];
    const float4* y0 = (const float4*)(g_y + (size_t)e0 * DD);
    const float4* y1 = (const float4*)(g_y + (size_t)e1 * DD);
    float4*       o  = (float4*)(out + (size_t)t * DD);
    int i = threadIdx.x;
    float4 a = y0[i], b = y1[i];
    o[i] = make_float4(fmaf(w0, a.x, w1 * b.x), fmaf(w0, a.y, w1 * b.y),
                       fmaf(w0, a.z, w1 * b.z), fmaf(w0, a.w, w1 * b.w));
}

// ------------------------- fp16 mma.sync GEMM -------------------------
// CTA tile 128x256; 8 warps, warp tile 64x64 (2m x 4n); K chunk 64.
// A fp16 [m][k] via ldmatrix.x4; B fp16 [k][n] via ldmatrix.x4.trans.
// 4-stage cp.async, 2-chunk groups: ONE wait+barrier per 2 chunks.
// Register double-buffered fragments, in-group tail prefetch.
// Compact grid: blockIdx.x indexes g_map (expert, m-tile).
#define SA_H 72                     // A row stride, halves
#define SB_H 264                    // B row stride, halves
#define A_ST (128 * SA_H * 2)       // 18432 B
#define B_ST (64 * SB_H * 2)        // 33792 B
#define STG_B (A_ST + B_ST)         // 52224 B
#define NSTG 4

template <int DO_GELU>
__global__ void __launch_bounds__(256, 1)
moe_ffn_h(const __half* __restrict__ A, const __half* __restrict__ B,
          const float* __restrict__ bias, void* __restrict__ OutV,
          int K, int Ntot) {
    if ((int)blockIdx.x >= g_nmt) return;
    int em = g_map[blockIdx.x];
    int e  = em >> 16;
    int m0 = (em & 0xFFFF) << 7;
    int cnt  = g_cnt[e];
    int base = g_base[e];
    int n0   = blockIdx.y * 256;

    extern __shared__ __align__(16) char smem[];
    uint32_t sb = s2u(smem);
    float* sBias = (float*)(smem + NSTG * STG_B);

    int tid  = threadIdx.x;
    int lane = tid & 31, w = tid >> 5;
    int g = lane >> 2, tg = lane & 3;
    int wm = w & 1, wn = w >> 1;

    uint32_t aLane = (uint32_t)(((wm * 64 + (lane & 7) + ((lane >> 3) & 1) * 8) * SA_H
                                 + ((lane >> 4) & 1) * 8) * 2);
    uint32_t bLane = (uint32_t)((((lane & 7) + ((lane >> 3) & 1) * 8) * SB_H
                                 + ((lane >> 4) & 1) * 8 + wn * 64) * 2);

    sBias[tid] = bias[(size_t)e * Ntot + n0 + tid];

    const __half* Ab = A + (size_t)(base + m0) * K;
    const __half* Bb = B + (size_t)e * K * Ntot + n0;
    int C = K >> 6;
    int G = C >> 1;                  // 2-chunk groups; C even (16 or 64)

    auto load_part = [&](int c, int s, int part) {  // parts 0..3, 3 cp16 each
        {
            int i = tid + part * 256;
            int m = i >> 3, seg = i & 7;
            cp16(sb + (uint32_t)s * STG_B + (uint32_t)((m * SA_H + seg * 8) * 2),
                 Ab + (size_t)m * K + c * 64 + seg * 8);
        }
        #pragma unroll
        for (int jj = 0; jj < 2; jj++) {
            int i = tid + (part * 2 + jj) * 256;
            int k = i >> 5, seg = i & 31;
            cp16(sb + (uint32_t)s * STG_B + A_ST + (uint32_t)((k * SB_H + seg * 8) * 2),
                 Bb + (size_t)(c * 64 + k) * Ntot + seg * 8);
        }
    };
    auto load_full = [&](int c, int s) {
        #pragma unroll
        for (int p = 0; p < 4; p++) load_part(c, s, p);
    };

    auto ldfragA = [&](uint32_t af[4][4], int s, int ks) {
        uint32_t stgA = sb + (uint32_t)s * STG_B + aLane + (uint32_t)(ks * 32);
        #pragma unroll
        for (int mt = 0; mt < 4; mt++)
            ldm4(af[mt], stgA + (uint32_t)(mt * 16 * SA_H * 2));
    };
    auto ldfragB = [&](uint32_t bf[4][4], int s, int ks) {
        uint32_t stgB = sb + (uint32_t)s * STG_B + A_ST + bLane
                      + (uint32_t)(ks * 16 * SB_H * 2);
        #pragma unroll
        for (int nb = 0; nb < 4; nb++)
            ldm4t(bf[nb], stgB + (uint32_t)(nb * 32));
    };

    // preload groups 0 and 1 (chunks 0..3 -> stages 0..3), one commit per group
    load_full(0, 0); load_full(1, 1);
    asm volatile("cp.async.commit_group;" ::: "memory");
    load_full(2, 2); load_full(3, 3);
    asm volatile("cp.async.commit_group;" ::: "memory");

    float acc[4][8][4];
    #pragma unroll
    for (int mt = 0; mt < 4; mt++)
        #pragma unroll
        for (int nt = 0; nt < 8; nt++)
            #pragma unroll
            for (int q = 0; q < 4; q++) acc[mt][nt][q] = 0.f;

    uint32_t af[2][4][4], bf[2][4][4];

    for (int j = 0; j < G; j++) {
        int s0 = (2 * j) & 3, s1 = s0 + 1;
        if (j == 0) { asm volatile("cp.async.wait_group 1;" ::: "memory"); }
        else        { asm volatile("cp.async.wait_group 0;" ::: "memory"); }
        __syncthreads();

        ldfragA(af[0], s0, 0); ldfragB(bf[0], s0, 0);

        bool ld = (j >= 1) && (j + 1 < G);   // group j+1 -> group j-1's stages
        int t0 = (s0 + 2) & 3, t1 = t0 + 1;

        // ---- chunk a = 2j (stage s0); front-load next group's slices ----
        #pragma unroll
        for (int ks = 0; ks < 4; ks++) {
            int cur = ks & 1;
            if (ks < 3) { ldfragA(af[cur ^ 1], s0, ks + 1); ldfragB(bf[cur ^ 1], s0, ks + 1); }
            else        { ldfragA(af[cur ^ 1], s1, 0);      ldfragB(bf[cur ^ 1], s1, 0); }
            if (ld) { load_part(2 * j + 2, t0, ks); load_part(2 * j + 3, t1, ks); }
            #pragma unroll
            for (int mt = 0; mt < 4; mt++)
                #pragma unroll
                for (int nt = 0; nt < 8; nt++) {
                    int p = nt >> 1, q = (nt & 1) * 2;
                    mma16(acc[mt][nt], af[cur][mt], bf[cur][p][q], bf[cur][p][q + 1]);
                }
        }
        if (ld) asm volatile("cp.async.commit_group;" ::: "memory");

        // ---- chunk b = 2j+1 (stage s1) ----
        #pragma unroll
        for (int ks = 0; ks < 4; ks++) {
            int cur = ks & 1;
            if (ks < 3) { ldfragA(af[cur ^ 1], s1, ks + 1); ldfragB(bf[cur ^ 1], s1, ks + 1); }
            #pragma unroll
            for (int mt = 0; mt < 4; mt++)
                #pragma unroll
                for (int nt = 0; nt < 8; nt++) {
                    int p = nt >> 1, q = (nt & 1) * 2;
                    mma16(acc[mt][nt], af[cur][mt], bf[cur][p][q], bf[cur][p][q + 1]);
                }
        }
    }

    // epilogue: bias (+gelu for FFN1); FFN1 writes fp16, FFN2 writes fp32
    #pragma unroll
    for (int mt = 0; mt < 4; mt++) {
        int r0 = m0 + wm * 64 + mt * 16 + g;
        #pragma unroll
        for (int half = 0; half < 2; half++) {
            int r = r0 + half * 8;
            if (r < cnt) {
                size_t orow = (size_t)(base + r) * Ntot + n0;
                #pragma unroll
                for (int nt = 0; nt < 8; nt++) {
                    int col = wn * 64 + nt * 8 + 2 * tg;
                    float v0 = acc[mt][nt][half * 2 + 0] + sBias[col];
                    float v1 = acc[mt][nt][half * 2 + 1] + sBias[col + 1];
                    if (DO_GELU) {
                        v0 = gelu_fast(v0); v1 = gelu_fast(v1);
                        uint32_t hv = f2h2(v0, v1);
                        *(uint32_t*)((__half*)OutV + orow + col) = hv;
                    } else {
                        *(float2*)((float*)OutV + orow + col) = make_float2(v0, v1);
                    }
                }
            }
        }
    }
}

// ------------------------- launcher -------------------------
extern "C" void kernel_launch(void* const* d_in, const int* in_sizes, int n_in,
                              void* d_out, int out_size) {
    const float* x  = (const float*)d_in[0];
    const float* gw = (const float*)d_in[1];
    const float* gb = (const float*)d_in[2];
    const float* w1 = (const float*)d_in[3];
    const float* b1 = (const float*)d_in[4];
    const float* w2 = (const float*)d_in[5];
    const float* b2 = (const float*)d_in[6];
    float* out = (float*)d_out;

    void *pw1, *pw2, *pxe, *ph, *py;
    cudaGetSymbolAddress(&pw1, g_w1h);
    cudaGetSymbolAddress(&pw2, g_w2h);
    cudaGetSymbolAddress(&pxe, g_xe16);
    cudaGetSymbolAddress(&ph,  g_h16);
    cudaGetSymbolAddress(&py,  g_y);

    size_t smem = NSTG * STG_B + 256 * sizeof(float) + 64;  // ~205 KB
    cudaFuncSetAttribute(moe_ffn_h<1>,
                         cudaFuncAttributeMaxDynamicSharedMemorySize, (int)smem);
    cudaFuncSetAttribute(moe_ffn_h<0>,
                         cudaFuncAttributeMaxDynamicSharedMemorySize, (int)smem);

    moe_reset_kernel<<<1, 32>>>();
    // fused: gate + both weight fp16 conversions in one launch
    moe_prep_kernel<<<GATE_BLKS + 2 * WCVT_BLKS, 256>>>(
        x, gw, gb, (const float4*)w1, (uint4*)pw1, (const float4*)w2, (uint4*)pw2);
    moe_tilemap_kernel<<<1, 32>>>();
    moe_gather_kernel<<<dim3(64, NE), 256>>>(x);
    // FFN1: g_h16 = fp16(gelu(x @ w1 + b1))
    moe_ffn_h<1><<<dim3(MAXMT, HH / 256), 256, smem>>>(
        (const __half*)pxe, (const __half*)pw1, b1, ph, DD, HH);
    // FFN2: g_y = h @ w2 + b2
    moe_ffn_h<0><<<dim3(MAXMT, DD / 256), 256, smem>>>(
        (const __half*)ph, (const __half*)pw2, b2, py, HH, DD);
    moe_combine_kernel<<<NT, 256>>>(out);
}